// round 8
// baseline (speedup 1.0000x reference)
#include <cuda_runtime.h>
#include <cuda_bf16.h>

// 3D ROI pooling — single-wave, max-MLP version (guard fixed).
//   img:  (1, 256, 256, 256, 8) fp32, layout ((ix*256+iy)*256+iz)*8 + c
//   rois: (1, 64, 6) int32  [x, y, z, w, h, d]
//   out:  (1, 64, 7, 7, 7, 8) fp32
//
// One thread per cell (roi, px, py, pz), padded to 8^3 slots per roi:
//   tid = roi<<9 | px<<6 | py<<3 | pz          (32768 threads)
// Grid = 128 CTAs x 256 threads -> exactly one wave on 148 SMs. Each thread
// issues 16 independent LDG.128 (8 corners x 2 channel-halves).

#define NUM_ROIS 64
#define PS 7
#define CELLS (PS * PS * PS)            // 343
#define DIM 256

__global__ void __launch_bounds__(256) roi_pool3d_kernel(
    const float* __restrict__ img,
    const int* __restrict__ rois,
    float* __restrict__ out)
{
    int tid = blockIdx.x * 256 + threadIdx.x;   // 0 .. 32767

    int pz  = tid & 7;
    int py  = (tid >> 3) & 7;
    int px  = (tid >> 6) & 7;
    int roi = tid >> 9;

    if (px == 7 || py == 7 || pz == 7) return;   // padding lanes only

    // roi row = 6 ints at byte offset 24*roi -> 8B aligned: three int2 loads
    const int2* r2p = (const int2*)(rois + roi * 6);
    int2 rxy = __ldg(r2p + 0);    // x, y
    int2 rzw = __ldg(r2p + 1);    // z, w
    int2 rhd = __ldg(r2p + 2);    // h, d
    int x = rxy.x, y = rxy.y, z = rzw.x;
    int w = rzw.y, h = rhd.x, d = rhd.y;

    // --- axis coords (match reference fp32 arithmetic exactly) ---
    float sx = (float)px * ((float)w / (float)PS);
    int ix0 = (int)floorf(sx);
    float fx = sx - (float)ix0;
    int ix1 = min(ix0 + 1, w - 1);
    ix0 = min(ix0, w - 1);

    float sy = (float)py * ((float)h / (float)PS);
    int iy0 = (int)floorf(sy);
    float fy = sy - (float)iy0;
    int iy1 = min(iy0 + 1, h - 1);
    iy0 = min(iy0, h - 1);

    float sz = (float)pz * ((float)d / (float)PS);
    int iz0 = (int)floorf(sz);
    float fz = sz - (float)iz0;
    int iz1 = min(iz0 + 1, d - 1);
    iz0 = min(iz0, d - 1);

    int jx0 = x + ix0, jx1 = x + ix1;
    int jy0 = y + iy0, jy1 = y + iy1;
    int jz0 = z + iz0, jz1 = z + iz1;

    const float4* __restrict__ base = (const float4*)img;
    int row00 = (jx0 * DIM + jy0) * DIM;
    int row01 = (jx0 * DIM + jy1) * DIM;
    int row10 = (jx1 * DIM + jy0) * DIM;
    int row11 = (jx1 * DIM + jy1) * DIM;

    size_t a000 = (size_t)(row00 + jz0) * 2;
    size_t a001 = (size_t)(row00 + jz1) * 2;
    size_t a010 = (size_t)(row01 + jz0) * 2;
    size_t a011 = (size_t)(row01 + jz1) * 2;
    size_t a100 = (size_t)(row10 + jz0) * 2;
    size_t a101 = (size_t)(row10 + jz1) * 2;
    size_t a110 = (size_t)(row11 + jz0) * 2;
    size_t a111 = (size_t)(row11 + jz1) * 2;

    // 16 independent LDG.128 (MLP = 16)
    float4 v000a = base[a000],     v000b = base[a000 + 1];
    float4 v001a = base[a001],     v001b = base[a001 + 1];
    float4 v010a = base[a010],     v010b = base[a010 + 1];
    float4 v011a = base[a011],     v011b = base[a011 + 1];
    float4 v100a = base[a100],     v100b = base[a100 + 1];
    float4 v101a = base[a101],     v101b = base[a101 + 1];
    float4 v110a = base[a110],     v110b = base[a110 + 1];
    float4 v111a = base[a111],     v111b = base[a111 + 1];

    float gz = 1.0f - fz, gy = 1.0f - fy, gx = 1.0f - fx;

    float4 oa, ob;
    {
        float c00, c01, c10, c11, c0, c1;

        // half A
        c00 = v000a.x * gz + v001a.x * fz;
        c01 = v010a.x * gz + v011a.x * fz;
        c10 = v100a.x * gz + v101a.x * fz;
        c11 = v110a.x * gz + v111a.x * fz;
        c0 = c00 * gy + c01 * fy;  c1 = c10 * gy + c11 * fy;
        oa.x = c0 * gx + c1 * fx;

        c00 = v000a.y * gz + v001a.y * fz;
        c01 = v010a.y * gz + v011a.y * fz;
        c10 = v100a.y * gz + v101a.y * fz;
        c11 = v110a.y * gz + v111a.y * fz;
        c0 = c00 * gy + c01 * fy;  c1 = c10 * gy + c11 * fy;
        oa.y = c0 * gx + c1 * fx;

        c00 = v000a.z * gz + v001a.z * fz;
        c01 = v010a.z * gz + v011a.z * fz;
        c10 = v100a.z * gz + v101a.z * fz;
        c11 = v110a.z * gz + v111a.z * fz;
        c0 = c00 * gy + c01 * fy;  c1 = c10 * gy + c11 * fy;
        oa.z = c0 * gx + c1 * fx;

        c00 = v000a.w * gz + v001a.w * fz;
        c01 = v010a.w * gz + v011a.w * fz;
        c10 = v100a.w * gz + v101a.w * fz;
        c11 = v110a.w * gz + v111a.w * fz;
        c0 = c00 * gy + c01 * fy;  c1 = c10 * gy + c11 * fy;
        oa.w = c0 * gx + c1 * fx;

        // half B
        c00 = v000b.x * gz + v001b.x * fz;
        c01 = v010b.x * gz + v011b.x * fz;
        c10 = v100b.x * gz + v101b.x * fz;
        c11 = v110b.x * gz + v111b.x * fz;
        c0 = c00 * gy + c01 * fy;  c1 = c10 * gy + c11 * fy;
        ob.x = c0 * gx + c1 * fx;

        c00 = v000b.y * gz + v001b.y * fz;
        c01 = v010b.y * gz + v011b.y * fz;
        c10 = v100b.y * gz + v101b.y * fz;
        c11 = v110b.y * gz + v111b.y * fz;
        c0 = c00 * gy + c01 * fy;  c1 = c10 * gy + c11 * fy;
        ob.y = c0 * gx + c1 * fx;

        c00 = v000b.z * gz + v001b.z * fz;
        c01 = v010b.z * gz + v011b.z * fz;
        c10 = v100b.z * gz + v101b.z * fz;
        c11 = v110b.z * gz + v111b.z * fz;
        c0 = c00 * gy + c01 * fy;  c1 = c10 * gy + c11 * fy;
        ob.z = c0 * gx + c1 * fx;

        c00 = v000b.w * gz + v001b.w * fz;
        c01 = v010b.w * gz + v011b.w * fz;
        c10 = v100b.w * gz + v101b.w * fz;
        c11 = v110b.w * gz + v111b.w * fz;
        c0 = c00 * gy + c01 * fy;  c1 = c10 * gy + c11 * fy;
        ob.w = c0 * gx + c1 * fx;
    }

    // output: (roi*343 + (px*7+py)*7+pz) * 2 float4s
    int cell = (px * PS + py) * PS + pz;
    float4* op = (float4*)out + (size_t)(roi * CELLS + cell) * 2;
    op[0] = oa;
    op[1] = ob;
}

extern "C" void kernel_launch(void* const* d_in, const int* in_sizes, int n_in,
                              void* d_out, int out_size)
{
    const float* img  = (const float*)d_in[0];
    const int*   rois = (const int*)d_in[1];
    float*       out  = (float*)d_out;

    // 64 rois * 512 padded slots = 32768 threads = 128 CTAs x 256 (single wave)
    roi_pool3d_kernel<<<128, 256>>>(img, rois, out);
}